// round 1
// baseline (speedup 1.0000x reference)
#include <cuda_runtime.h>
#include <math.h>

#define SDIM 2048
#define DDIM 64
#define TQ 16
#define NTHREADS 256
#define KPAD 68   // 64 + 4 pad: conflict-free LDS patterns

// smem layout (floats):
//   sc   [TQ][SDIM]      = 32768
//   qs   [TQ][DDIM]      = 1024
//   ks   [64][KPAD]      = 4352   (reused for v chunks)
//   sinv [TQ]            = 16
#define SMEM_FLOATS (TQ*SDIM + TQ*DDIM + 64*KPAD + TQ)

__global__ __launch_bounds__(NTHREADS, 1)
void attn_fused_kernel(const float* __restrict__ qg,
                       const float* __restrict__ kg,
                       const float* __restrict__ vg,
                       float* __restrict__ outg,
                       float* __restrict__ attng) {
    const int bh    = blockIdx.y;
    const int qbase = blockIdx.x * TQ;
    const int tid   = threadIdx.x;

    extern __shared__ float sm[];
    float* sc   = sm;                      // [TQ][SDIM] scores -> exp(p)
    float* qs   = sc + TQ * SDIM;          // [TQ][DDIM]
    float* ks   = qs + TQ * DDIM;          // [64][KPAD] k chunk, later v chunk
    float* sinv = ks + 64 * KPAD;          // [TQ] 1/rowsum

    const size_t headoff = (size_t)bh * SDIM * DDIM;
    const float* qp = qg + headoff + (size_t)qbase * DDIM;
    const float* kp = kg + headoff;
    const float* vp = vg + headoff;

    // ---- load q tile, pre-scaled by 1/8 ----
    for (int idx = tid; idx < TQ * DDIM; idx += NTHREADS)
        qs[idx] = qp[idx] * 0.125f;

    const int L       = qbase + TQ;        // max valid cols in this tile
    const int nChunks = (L + 63) >> 6;

    const int j  = tid & 63;               // key col within chunk / d for PV
    const int i0 = tid >> 6;               // 0..3; rows i0, i0+4, i0+8, i0+12

    // ================= QK^T =================
    for (int c = 0; c < nChunks; ++c) {
        const int jbase = c << 6;
        __syncthreads();  // protect ks from previous iteration's readers
        {
            const float4* src = (const float4*)(kp + (size_t)jbase * DDIM);
            #pragma unroll
            for (int rep = 0; rep < 4; ++rep) {
                int lin = tid + rep * NTHREADS;   // 1024 float4s
                int row = lin >> 4;
                int c4  = lin & 15;
                float4 val = src[lin];
                *(float4*)(ks + row * KPAD + c4 * 4) = val;
            }
        }
        __syncthreads();

        float acc0 = 0.f, acc1 = 0.f, acc2 = 0.f, acc3 = 0.f;
        const float4* kr = (const float4*)(ks + j * KPAD);
        #pragma unroll
        for (int d4 = 0; d4 < 16; ++d4) {
            float4 kv = kr[d4];
            float4 q0 = *(const float4*)(qs + (i0     ) * DDIM + d4 * 4);
            float4 q1 = *(const float4*)(qs + (i0 +  4) * DDIM + d4 * 4);
            float4 q2 = *(const float4*)(qs + (i0 +  8) * DDIM + d4 * 4);
            float4 q3 = *(const float4*)(qs + (i0 + 12) * DDIM + d4 * 4);
            acc0 += kv.x*q0.x + kv.y*q0.y + kv.z*q0.z + kv.w*q0.w;
            acc1 += kv.x*q1.x + kv.y*q1.y + kv.z*q1.z + kv.w*q1.w;
            acc2 += kv.x*q2.x + kv.y*q2.y + kv.z*q2.z + kv.w*q2.w;
            acc3 += kv.x*q3.x + kv.y*q3.y + kv.z*q3.z + kv.w*q3.w;
        }
        sc[(i0     ) * SDIM + jbase + j] = acc0;
        sc[(i0 +  4) * SDIM + jbase + j] = acc1;
        sc[(i0 +  8) * SDIM + jbase + j] = acc2;
        sc[(i0 + 12) * SDIM + jbase + j] = acc3;
    }
    __syncthreads();

    // ================= softmax (16 threads per row) =================
    {
        const int r   = tid >> 4;
        const int l16 = tid & 15;
        const int Lr  = qbase + r + 1;     // causal valid length
        float* srow = sc + r * SDIM;

        float m = -1e30f;
        for (int jj = l16; jj < Lr; jj += 16)
            m = fmaxf(m, srow[jj]);
        #pragma unroll
        for (int o = 8; o > 0; o >>= 1)
            m = fmaxf(m, __shfl_xor_sync(0xffffffffu, m, o, 16));

        float s = 0.f;
        for (int jj = l16; jj < Lr; jj += 16) {
            float p = __expf(srow[jj] - m);
            srow[jj] = p;
            s += p;
        }
        #pragma unroll
        for (int o = 8; o > 0; o >>= 1)
            s += __shfl_xor_sync(0xffffffffu, s, o, 16);
        if (l16 == 0) sinv[r] = 1.0f / s;

        // zero the garbage tail [Lr, nChunks*64) so PV can run full chunks
        const int cend = nChunks << 6;
        for (int jj = Lr + l16; jj < cend; jj += 16)
            srow[jj] = 0.f;
    }
    __syncthreads();

    // ================= attn matrix write =================
    if (attng) {
        #pragma unroll 1
        for (int r = 0; r < TQ; ++r) {
            const int Lr = qbase + r + 1;
            const float invr = sinv[r];
            float* arow = attng + ((size_t)bh * SDIM + qbase + r) * SDIM;
            const float* srow = sc + r * SDIM;
            for (int jj = tid; jj < SDIM; jj += NTHREADS)
                arow[jj] = (jj < Lr) ? srow[jj] * invr : 0.f;
        }
    }

    // ================= PV =================
    float o0 = 0.f, o1 = 0.f, o2 = 0.f, o3 = 0.f;
    const int d = j;
    for (int c = 0; c < nChunks; ++c) {
        const int jbase = c << 6;
        __syncthreads();  // previous chunk consumed
        {
            const float4* src = (const float4*)(vp + (size_t)jbase * DDIM);
            #pragma unroll
            for (int rep = 0; rep < 4; ++rep) {
                int lin = tid + rep * NTHREADS;
                int row = lin >> 4;
                int c4  = lin & 15;
                float4 val = src[lin];
                *(float4*)(ks + row * KPAD + c4 * 4) = val;
            }
        }
        __syncthreads();

        #pragma unroll 4
        for (int jj4 = 0; jj4 < 16; ++jj4) {
            float4 p0 = *(const float4*)(sc + (i0     ) * SDIM + jbase + jj4 * 4);
            float4 p1 = *(const float4*)(sc + (i0 +  4) * SDIM + jbase + jj4 * 4);
            float4 p2 = *(const float4*)(sc + (i0 +  8) * SDIM + jbase + jj4 * 4);
            float4 p3 = *(const float4*)(sc + (i0 + 12) * SDIM + jbase + jj4 * 4);
            float v0 = ks[(jj4 * 4    ) * KPAD + d];
            float v1 = ks[(jj4 * 4 + 1) * KPAD + d];
            float v2 = ks[(jj4 * 4 + 2) * KPAD + d];
            float v3 = ks[(jj4 * 4 + 3) * KPAD + d];
            o0 += p0.x*v0 + p0.y*v1 + p0.z*v2 + p0.w*v3;
            o1 += p1.x*v0 + p1.y*v1 + p1.z*v2 + p1.w*v3;
            o2 += p2.x*v0 + p2.y*v1 + p2.z*v2 + p2.w*v3;
            o3 += p3.x*v0 + p3.y*v1 + p3.z*v2 + p3.w*v3;
        }
    }

    float* orow = outg + headoff + (size_t)qbase * DDIM;
    orow[(i0     ) * DDIM + d] = o0 * sinv[i0];
    orow[(i0 +  4) * DDIM + d] = o1 * sinv[i0 + 4];
    orow[(i0 +  8) * DDIM + d] = o2 * sinv[i0 + 8];
    orow[(i0 + 12) * DDIM + d] = o3 * sinv[i0 + 12];
}

extern "C" void kernel_launch(void* const* d_in, const int* in_sizes, int n_in,
                              void* d_out, int out_size) {
    const float* q = (const float*)d_in[0];
    const float* k = (const float*)d_in[1];
    const float* v = (const float*)d_in[2];
    // d_in[3] is the causal mask; shape is known, so it is not read.

    float* out = (float*)d_out;

    const long long OUT_E  = 64LL * 2048 * 64;      //   8,388,608
    const long long ATTN_E = 64LL * 2048 * 2048;    // 268,435,456

    float* attn = nullptr;
    if ((long long)out_size >= OUT_E + ATTN_E)
        attn = out + OUT_E;                          // (output, attn) flattened

    const size_t smem_bytes = SMEM_FLOATS * sizeof(float);
    cudaFuncSetAttribute(attn_fused_kernel,
                         cudaFuncAttributeMaxDynamicSharedMemorySize,
                         (int)smem_bytes);

    dim3 grid(SDIM / TQ, 64);   // 128 q-tiles x 64 (b,h) heads
    dim3 block(NTHREADS);
    attn_fused_kernel<<<grid, block, smem_bytes>>>(q, k, v, out, attn);
}

// round 2
// speedup vs baseline: 1.0031x; 1.0031x over previous
#include <cuda_runtime.h>
#include <cuda_bf16.h>
#include <stdint.h>
#include <math.h>

#define SDIM 2048
#define DDIM 64
#define TQ 16
#define NTHREADS 256
#define SCSTR 2056          // sc row stride (floats): 8 mod 32 -> conflict-free LDS.64
#define KSTR  72            // staged bf16 row stride (uint16): 144B -> conflict-free LDS.32

// smem byte layout
#define OFF_SC   0
#define OFF_QS   131584     // 16*2056*4
#define OFF_KH   135680     // +16*64*4
#define OFF_KL   144896     // +64*72*2
#define OFF_SINV 154112     // +64*72*2
#define SMEM_BYTES 154176   // +16*4

__device__ __forceinline__ void mma16816(float c[4], const uint32_t a[4], const uint32_t b[2]) {
    asm volatile(
        "mma.sync.aligned.m16n8k16.row.col.f32.bf16.bf16.f32 "
        "{%0,%1,%2,%3}, {%4,%5,%6,%7}, {%8,%9}, {%0,%1,%2,%3};\n"
        : "+f"(c[0]), "+f"(c[1]), "+f"(c[2]), "+f"(c[3])
        : "r"(a[0]), "r"(a[1]), "r"(a[2]), "r"(a[3]), "r"(b[0]), "r"(b[1]));
}

// split two fp32 into packed bf16x2 (hi parts) and bf16x2 (lo residuals); low half = first elem
__device__ __forceinline__ void split2(float x, float y, uint32_t &hi, uint32_t &lo) {
    __nv_bfloat16 hx = __float2bfloat16(x);
    __nv_bfloat16 hy = __float2bfloat16(y);
    float rx = x - __bfloat162float(hx);
    float ry = y - __bfloat162float(hy);
    __nv_bfloat16 lx = __float2bfloat16(rx);
    __nv_bfloat16 ly = __float2bfloat16(ry);
    hi = ((uint32_t)__bfloat16_as_ushort(hy) << 16) | (uint32_t)__bfloat16_as_ushort(hx);
    lo = ((uint32_t)__bfloat16_as_ushort(ly) << 16) | (uint32_t)__bfloat16_as_ushort(lx);
}

__device__ __forceinline__ void split1(float x, uint16_t &h, uint16_t &l) {
    __nv_bfloat16 hx = __float2bfloat16(x);
    float rx = x - __bfloat162float(hx);
    h = __bfloat16_as_ushort(hx);
    l = __bfloat16_as_ushort(__float2bfloat16(rx));
}

// pack one fp32 as (lo16<<16)|hi16
__device__ __forceinline__ uint32_t pack_hl(float x) {
    __nv_bfloat16 hx = __float2bfloat16(x);
    float rx = x - __bfloat162float(hx);
    __nv_bfloat16 lx = __float2bfloat16(rx);
    return ((uint32_t)__bfloat16_as_ushort(lx) << 16) | (uint32_t)__bfloat16_as_ushort(hx);
}

__global__ __launch_bounds__(NTHREADS, 1)
void attn_mma_kernel(const float* __restrict__ qg, const float* __restrict__ kg,
                     const float* __restrict__ vg, float* __restrict__ outg,
                     float* __restrict__ attng)
{
    extern __shared__ char smraw[];
    float*    sc   = (float*)(smraw + OFF_SC);     // [16][SCSTR] fp32 scores -> packed bf16 hi/lo
    float*    qs   = (float*)(smraw + OFF_QS);     // [16][64] fp32 q (scaled)
    uint16_t* khm  = (uint16_t*)(smraw + OFF_KH);  // [64][KSTR] bf16 hi (K chunk / V^T chunk)
    uint16_t* klm  = (uint16_t*)(smraw + OFF_KL);  // [64][KSTR] bf16 lo
    float*    sinv = (float*)(smraw + OFF_SINV);   // [16]

    const int bh    = blockIdx.y;
    const int qbase = blockIdx.x * TQ;
    const int tid   = threadIdx.x;
    const int lane  = tid & 31;
    const int wid   = tid >> 5;

    const size_t headoff = (size_t)bh * SDIM * DDIM;
    const float* qp = qg + headoff + (size_t)qbase * DDIM;
    const float* kp = kg + headoff;
    const float* vp = vg + headoff;

    // stage q (pre-scaled by 1/8)
    for (int idx = tid; idx < TQ * DDIM; idx += NTHREADS)
        qs[idx] = qp[idx] * 0.125f;
    __syncthreads();

    const int r4 = lane >> 2;          // 0..7
    const int c0 = (lane & 3) * 2;     // 0,2,4,6
    const int nChunks = (qbase + TQ + 63) >> 6;
    const int cend = nChunks << 6;

    // ---- Q A-fragments in registers (shared by all chunks) ----
    uint32_t aqh[4][4], aql[4][4];
    #pragma unroll
    for (int ks = 0; ks < 4; ++ks) {
        const float* q0 = qs + r4 * DDIM + ks * 16;
        const float* q1 = qs + (r4 + 8) * DDIM + ks * 16;
        split2(q0[c0],     q0[c0 + 1], aqh[ks][0], aql[ks][0]);
        split2(q1[c0],     q1[c0 + 1], aqh[ks][1], aql[ks][1]);
        split2(q0[c0 + 8], q0[c0 + 9], aqh[ks][2], aql[ks][2]);
        split2(q1[c0 + 8], q1[c0 + 9], aqh[ks][3], aql[ks][3]);
    }

    // ================= QK^T (tensor core) =================
    for (int c = 0; c < nChunks; ++c) {
        const int jbase = c << 6;
        __syncthreads();
        {   // stage K chunk -> bf16 hi/lo, rows [key][d]
            const float4* src = (const float4*)(kp + (size_t)jbase * DDIM);
            #pragma unroll
            for (int rep = 0; rep < 4; ++rep) {
                int lin = tid + rep * NTHREADS;    // 1024 float4
                int row = lin >> 4, c4 = lin & 15;
                float4 v = src[lin];
                uint32_t h0, l0, h1, l1;
                split2(v.x, v.y, h0, l0);
                split2(v.z, v.w, h1, l1);
                int off = row * KSTR + c4 * 4;
                *(uint2*)(khm + off) = make_uint2(h0, h1);
                *(uint2*)(klm + off) = make_uint2(l0, l1);
            }
        }
        __syncthreads();

        float acc[4] = {0.f, 0.f, 0.f, 0.f};
        const int keyb = (wid << 3) + (lane >> 2);   // B: n = lane>>2
        const int k0   = (lane & 3) * 2;             // B: k = (lane&3)*2
        #pragma unroll
        for (int ks = 0; ks < 4; ++ks) {
            const int d0 = ks * 16 + k0;
            uint32_t bh2[2], bl2[2];
            bh2[0] = *(const uint32_t*)(khm + keyb * KSTR + d0);
            bh2[1] = *(const uint32_t*)(khm + keyb * KSTR + d0 + 8);
            bl2[0] = *(const uint32_t*)(klm + keyb * KSTR + d0);
            bl2[1] = *(const uint32_t*)(klm + keyb * KSTR + d0 + 8);
            mma16816(acc, aqh[ks], bh2);
            mma16816(acc, aql[ks], bh2);
            mma16816(acc, aqh[ks], bl2);
        }
        const int colg = jbase + (wid << 3) + c0;
        *(float2*)(sc + r4 * SCSTR + colg)       = make_float2(acc[0], acc[1]);
        *(float2*)(sc + (r4 + 8) * SCSTR + colg) = make_float2(acc[2], acc[3]);
    }
    __syncthreads();

    // ================= softmax (16 threads / row) =================
    {
        const int r   = tid >> 4;
        const int l16 = tid & 15;
        const int Lr  = qbase + r + 1;
        float* srow = sc + r * SCSTR;

        float m = -1e30f;
        for (int jj = l16; jj < Lr; jj += 16) m = fmaxf(m, srow[jj]);
        #pragma unroll
        for (int o = 8; o > 0; o >>= 1) m = fmaxf(m, __shfl_xor_sync(0xffffffffu, m, o, 16));

        float s = 0.f;
        for (int jj = l16; jj < Lr; jj += 16) {
            float p = __expf(srow[jj] - m);
            srow[jj] = p;
            s += p;
        }
        #pragma unroll
        for (int o = 8; o > 0; o >>= 1) s += __shfl_xor_sync(0xffffffffu, s, o, 16);
        if (l16 == 0) sinv[r] = 1.0f / s;

        // zero tail (incl. masked diagonal-chunk entries) so PV runs full chunks
        for (int jj = Lr + l16; jj < cend; jj += 16) srow[jj] = 0.f;
    }
    __syncthreads();

    // ======= attn global write + in-place pack of sc to bf16 hi/lo =======
    #pragma unroll 1
    for (int r = 0; r < TQ; ++r) {
        const float invr = sinv[r];
        float* srow = sc + r * SCSTR;
        float4* arow4 = attng ? (float4*)(attng + ((size_t)bh * SDIM + qbase + r) * SDIM)
                              : (float4*)0;
        #pragma unroll 1
        for (int jj = tid; jj < SDIM / 4; jj += NTHREADS) {
            const int j = jj * 4;
            if (j < cend) {
                float4 p = *(float4*)(srow + j);
                if (arow4) arow4[jj] = make_float4(p.x * invr, p.y * invr, p.z * invr, p.w * invr);
                uint4 pk;
                pk.x = pack_hl(p.x); pk.y = pack_hl(p.y);
                pk.z = pack_hl(p.z); pk.w = pack_hl(p.w);
                *(uint4*)(srow + j) = pk;
            } else if (arow4) {
                arow4[jj] = make_float4(0.f, 0.f, 0.f, 0.f);
            }
        }
    }
    __syncthreads();

    // ================= PV (tensor core) =================
    const uint32_t* scp = (const uint32_t*)sc;
    float oacc[4] = {0.f, 0.f, 0.f, 0.f};
    const int dcol = (wid << 3) + (lane >> 2);
    const int k0   = (lane & 3) * 2;
    for (int c = 0; c < nChunks; ++c) {
        const int jbase = c << 6;
        __syncthreads();
        {   // stage V chunk transposed -> vT[d][key], bf16 hi/lo
            const float4* src = (const float4*)(vp + (size_t)jbase * DDIM);
            #pragma unroll
            for (int rep = 0; rep < 4; ++rep) {
                int lin = tid + rep * NTHREADS;
                int key = lin >> 4, c4 = lin & 15;
                float4 v = src[lin];
                int d0 = c4 * 4;
                uint16_t h, l;
                split1(v.x, h, l); khm[(d0 + 0) * KSTR + key] = h; klm[(d0 + 0) * KSTR + key] = l;
                split1(v.y, h, l); khm[(d0 + 1) * KSTR + key] = h; klm[(d0 + 1) * KSTR + key] = l;
                split1(v.z, h, l); khm[(d0 + 2) * KSTR + key] = h; klm[(d0 + 2) * KSTR + key] = l;
                split1(v.w, h, l); khm[(d0 + 3) * KSTR + key] = h; klm[(d0 + 3) * KSTR + key] = l;
            }
        }
        __syncthreads();

        #pragma unroll
        for (int ks = 0; ks < 4; ++ks) {
            const int jb = jbase + ks * 16;
            // A from packed P: rows r4/r4+8, cols jb+c0(+1), jb+c0+8(+9)
            uint2 w01 = *(const uint2*)(scp + r4 * SCSTR + jb + c0);
            uint2 w23 = *(const uint2*)(scp + (r4 + 8) * SCSTR + jb + c0);
            uint2 w45 = *(const uint2*)(scp + r4 * SCSTR + jb + c0 + 8);
            uint2 w67 = *(const uint2*)(scp + (r4 + 8) * SCSTR + jb + c0 + 8);
            uint32_t ah[4], al[4];
            ah[0] = __byte_perm(w01.x, w01.y, 0x5410); al[0] = __byte_perm(w01.x, w01.y, 0x7632);
            ah[1] = __byte_perm(w23.x, w23.y, 0x5410); al[1] = __byte_perm(w23.x, w23.y, 0x7632);
            ah[2] = __byte_perm(w45.x, w45.y, 0x5410); al[2] = __byte_perm(w45.x, w45.y, 0x7632);
            ah[3] = __byte_perm(w67.x, w67.y, 0x5410); al[3] = __byte_perm(w67.x, w67.y, 0x7632);

            const int kk = ks * 16 + k0;
            uint32_t bh2[2], bl2[2];
            bh2[0] = *(const uint32_t*)(khm + dcol * KSTR + kk);
            bh2[1] = *(const uint32_t*)(khm + dcol * KSTR + kk + 8);
            bl2[0] = *(const uint32_t*)(klm + dcol * KSTR + kk);
            bl2[1] = *(const uint32_t*)(klm + dcol * KSTR + kk + 8);

            mma16816(oacc, ah, bh2);
            mma16816(oacc, al, bh2);
            mma16816(oacc, ah, bl2);
        }
    }

    // output: D frag (rows r4/r4+8, cols dc,dc+1), normalized
    float* orow = outg + headoff + (size_t)qbase * DDIM;
    const int dc = (wid << 3) + c0;
    *(float2*)(orow + r4 * DDIM + dc) =
        make_float2(oacc[0] * sinv[r4], oacc[1] * sinv[r4]);
    *(float2*)(orow + (r4 + 8) * DDIM + dc) =
        make_float2(oacc[2] * sinv[r4 + 8], oacc[3] * sinv[r4 + 8]);
}

extern "C" void kernel_launch(void* const* d_in, const int* in_sizes, int n_in,
                              void* d_out, int out_size) {
    const float* q = (const float*)d_in[0];
    const float* k = (const float*)d_in[1];
    const float* v = (const float*)d_in[2];
    // d_in[3] = causal mask; structure known, not read.

    float* out = (float*)d_out;
    const long long OUT_E  = 64LL * 2048 * 64;
    const long long ATTN_E = 64LL * 2048 * 2048;
    float* attn = ((long long)out_size >= OUT_E + ATTN_E) ? out + OUT_E : nullptr;

    cudaFuncSetAttribute(attn_mma_kernel,
                         cudaFuncAttributeMaxDynamicSharedMemorySize, SMEM_BYTES);

    dim3 grid(SDIM / TQ, 64);
    dim3 block(NTHREADS);
    attn_mma_kernel<<<grid, block, SMEM_BYTES>>>(q, k, v, out, attn);
}

// round 3
// speedup vs baseline: 2.1381x; 2.1315x over previous
#include <cuda_runtime.h>
#include <cuda_bf16.h>
#include <stdint.h>
#include <math.h>

#define SDIM 2048
#define DDIM 64
#define TQ 16
#define NTHREADS 512
#define CHUNK 128
#define SCSTR 2056     // sc row stride (floats): 8 mod 32 -> conflict-free LDS.64
#define KSTR  72       // K staging row stride (uint16): 144B
#define VSTR  136      // V^T staging row stride (uint16): 272B
#define BUFU  9216     // uint16 per sub-buffer (max of 128*72, 64*136)

// smem byte layout
#define OFF_SC    0
#define OFF_QS    131584            // 16*2056*4
#define OFF_STAGE 135680            // +16*64*4
#define OFF_SINV  209408            // +4*9216*2
#define SMEM_BYTES 209472

// global bf16 scratch (pre-converted), 64 heads
__device__ __align__(16) uint16_t g_khi[64u * 2048u * 64u];
__device__ __align__(16) uint16_t g_klo[64u * 2048u * 64u];
__device__ __align__(16) uint16_t g_vthi[64u * 64u * 2048u];   // [head][d][key]
__device__ __align__(16) uint16_t g_vtlo[64u * 64u * 2048u];

__device__ __forceinline__ void mma16816(float c[4], const uint32_t a[4], const uint32_t b[2]) {
    asm volatile(
        "mma.sync.aligned.m16n8k16.row.col.f32.bf16.bf16.f32 "
        "{%0,%1,%2,%3}, {%4,%5,%6,%7}, {%8,%9}, {%0,%1,%2,%3};\n"
        : "+f"(c[0]), "+f"(c[1]), "+f"(c[2]), "+f"(c[3])
        : "r"(a[0]), "r"(a[1]), "r"(a[2]), "r"(a[3]), "r"(b[0]), "r"(b[1]));
}

__device__ __forceinline__ void split2(float x, float y, uint32_t &hi, uint32_t &lo) {
    __nv_bfloat16 hx = __float2bfloat16(x);
    __nv_bfloat16 hy = __float2bfloat16(y);
    float rx = x - __bfloat162float(hx);
    float ry = y - __bfloat162float(hy);
    hi = ((uint32_t)__bfloat16_as_ushort(__float2bfloat16(y != y ? y : y)) & 0u) |
         (((uint32_t)__bfloat16_as_ushort(hy) << 16) | (uint32_t)__bfloat16_as_ushort(hx));
    lo = ((uint32_t)__bfloat16_as_ushort(__float2bfloat16(ry)) << 16) |
          (uint32_t)__bfloat16_as_ushort(__float2bfloat16(rx));
}

__device__ __forceinline__ void split1(float x, uint16_t &h, uint16_t &l) {
    __nv_bfloat16 hx = __float2bfloat16(x);
    h = __bfloat16_as_ushort(hx);
    l = __bfloat16_as_ushort(__float2bfloat16(x - __bfloat162float(hx)));
}

__device__ __forceinline__ uint32_t pack_hl(float x) {
    __nv_bfloat16 hx = __float2bfloat16(x);
    __nv_bfloat16 lx = __float2bfloat16(x - __bfloat162float(hx));
    return ((uint32_t)__bfloat16_as_ushort(lx) << 16) | (uint32_t)__bfloat16_as_ushort(hx);
}

__device__ __forceinline__ uint32_t s2u(const void* p) {
    return (uint32_t)__cvta_generic_to_shared(p);
}
__device__ __forceinline__ void cpa16(uint32_t dst, const void* src) {
    asm volatile("cp.async.cg.shared.global [%0], [%1], 16;\n" :: "r"(dst), "l"(src));
}
#define CP_COMMIT() asm volatile("cp.async.commit_group;\n" ::: "memory")
#define CP_WAIT1()  asm volatile("cp.async.wait_group 1;\n" ::: "memory")
#define CP_WAIT0()  asm volatile("cp.async.wait_group 0;\n" ::: "memory")

// ---------------- pre-convert kernels ----------------
__global__ void conv_k_kernel(const float* __restrict__ kg) {
    int idx = blockIdx.x * blockDim.x + threadIdx.x;   // float4 index
    float4 v = ((const float4*)kg)[idx];
    uint32_t h0, l0, h1, l1;
    split2(v.x, v.y, h0, l0);
    split2(v.z, v.w, h1, l1);
    *(uint2*)(g_khi + (size_t)idx * 4) = make_uint2(h0, h1);
    *(uint2*)(g_klo + (size_t)idx * 4) = make_uint2(l0, l1);
}

__global__ void conv_vt_kernel(const float* __restrict__ vg) {
    __shared__ uint16_t th[64 * KSTR];
    __shared__ uint16_t tl[64 * KSTR];
    const int head = blockIdx.y;
    const int kt   = blockIdx.x;          // 64-key tile
    const int tid  = threadIdx.x;         // 256
    const float* src = vg + (size_t)head * SDIM * DDIM + (size_t)kt * 64 * DDIM;
    #pragma unroll
    for (int rep = 0; rep < 4; ++rep) {
        int lin = tid + rep * 256;        // 1024 float4 = 64key x 16
        int key = lin >> 4, d4 = (lin & 15) * 4;
        float4 v = ((const float4*)src)[lin];
        uint16_t h, l;
        split1(v.x, h, l); th[(d4 + 0) * KSTR + key] = h; tl[(d4 + 0) * KSTR + key] = l;
        split1(v.y, h, l); th[(d4 + 1) * KSTR + key] = h; tl[(d4 + 1) * KSTR + key] = l;
        split1(v.z, h, l); th[(d4 + 2) * KSTR + key] = h; tl[(d4 + 2) * KSTR + key] = l;
        split1(v.w, h, l); th[(d4 + 3) * KSTR + key] = h; tl[(d4 + 3) * KSTR + key] = l;
    }
    __syncthreads();
    uint16_t* dsth = g_vthi + (size_t)head * 64 * SDIM + (size_t)kt * 64;
    uint16_t* dstl = g_vtlo + (size_t)head * 64 * SDIM + (size_t)kt * 64;
    #pragma unroll
    for (int rep = 0; rep < 2; ++rep) {
        int lin = tid + rep * 256;        // 512 = 64 rows x 8 x 16B
        int row = lin >> 3, c = (lin & 7) * 8;
        *(uint4*)(dsth + (size_t)row * SDIM + c) = *(uint4*)(th + row * KSTR + c);
        *(uint4*)(dstl + (size_t)row * SDIM + c) = *(uint4*)(tl + row * KSTR + c);
    }
}

// ---------------- main fused kernel ----------------
__global__ __launch_bounds__(NTHREADS, 1)
void attn_mma_kernel(const float* __restrict__ qg, float* __restrict__ outg,
                     float* __restrict__ attng)
{
    extern __shared__ char smraw[];
    float*    sc   = (float*)(smraw + OFF_SC);
    float*    qs   = (float*)(smraw + OFF_QS);
    uint16_t* stg  = (uint16_t*)(smraw + OFF_STAGE);
    float*    sinv = (float*)(smraw + OFF_SINV);

    const int bh    = blockIdx.y;
    const int qbase = blockIdx.x * TQ;
    const int tid   = threadIdx.x;
    const int lane  = tid & 31;
    const int wid   = tid >> 5;

    const size_t headoff = (size_t)bh * SDIM * DDIM;
    const uint16_t* khi = g_khi + headoff;
    const uint16_t* klo = g_klo + headoff;
    const uint16_t* vth = g_vthi + headoff;
    const uint16_t* vtl = g_vtlo + headoff;

    // stage q (pre-scaled)
    for (int idx = tid; idx < TQ * DDIM; idx += NTHREADS)
        qs[idx] = qg[headoff + (size_t)qbase * DDIM + idx] * 0.125f;
    __syncthreads();

    const int r4 = lane >> 2;
    const int c0 = (lane & 3) * 2;
    const int k0 = c0;
    const int nChunks = (qbase + TQ + CHUNK - 1) >> 7;
    const int cend = nChunks << 7;

    uint32_t aqh[4][4], aql[4][4];
    #pragma unroll
    for (int ks = 0; ks < 4; ++ks) {
        const float* q0 = qs + r4 * DDIM + ks * 16;
        const float* q1 = qs + (r4 + 8) * DDIM + ks * 16;
        split2(q0[c0],     q0[c0 + 1], aqh[ks][0], aql[ks][0]);
        split2(q1[c0],     q1[c0 + 1], aqh[ks][1], aql[ks][1]);
        split2(q0[c0 + 8], q0[c0 + 9], aqh[ks][2], aql[ks][2]);
        split2(q1[c0 + 8], q1[c0 + 9], aqh[ks][3], aql[ks][3]);
    }

    // ---- staging helpers (lambdas) ----
    auto stageK = [&](int buf, int cidx) {
        uint16_t* hi = stg + buf * 2 * BUFU;
        uint16_t* lo = hi + BUFU;
        const int jb = cidx << 7;
        #pragma unroll
        for (int rep = 0; rep < 2; ++rep) {
            int lin = tid + rep * NTHREADS;      // 1024: 128 keys x 8 (16B units)
            int key = lin >> 3, c16 = (lin & 7) * 8;
            cpa16(s2u(hi + key * KSTR + c16), khi + (size_t)(jb + key) * DDIM + c16);
            cpa16(s2u(lo + key * KSTR + c16), klo + (size_t)(jb + key) * DDIM + c16);
        }
    };
    auto stageV = [&](int buf, int cidx) {
        uint16_t* hi = stg + buf * 2 * BUFU;
        uint16_t* lo = hi + BUFU;
        const int jb = cidx << 7;
        #pragma unroll
        for (int rep = 0; rep < 2; ++rep) {
            int lin = tid + rep * NTHREADS;      // 1024: 64 rows x 16 (16B units)
            int row = lin >> 4, c16 = (lin & 15) * 8;
            cpa16(s2u(hi + row * VSTR + c16), vth + (size_t)row * SDIM + jb + c16);
            cpa16(s2u(lo + row * VSTR + c16), vtl + (size_t)row * SDIM + jb + c16);
        }
    };

    // ================= QK^T =================
    stageK(0, 0);
    CP_COMMIT();
    for (int c = 0; c < nChunks; ++c) {
        int cn = c + 1 < nChunks ? c + 1 : nChunks - 1;
        stageK((c + 1) & 1, cn);
        CP_COMMIT();
        CP_WAIT1();
        __syncthreads();

        const uint16_t* hib = stg + (c & 1) * 2 * BUFU;
        const uint16_t* lob = hib + BUFU;
        const int keyb = (wid << 3) + (lane >> 2);

        float acc[4] = {0.f, 0.f, 0.f, 0.f};
        #pragma unroll
        for (int ks = 0; ks < 4; ++ks) {
            const int d0 = ks * 16 + k0;
            uint32_t bh2[2], bl2[2];
            bh2[0] = *(const uint32_t*)(hib + keyb * KSTR + d0);
            bh2[1] = *(const uint32_t*)(hib + keyb * KSTR + d0 + 8);
            bl2[0] = *(const uint32_t*)(lob + keyb * KSTR + d0);
            bl2[1] = *(const uint32_t*)(lob + keyb * KSTR + d0 + 8);
            mma16816(acc, aqh[ks], bh2);
            mma16816(acc, aql[ks], bh2);
            mma16816(acc, aqh[ks], bl2);
        }
        const int colg = (c << 7) + (wid << 3) + c0;
        *(float2*)(sc + r4 * SCSTR + colg)       = make_float2(acc[0], acc[1]);
        *(float2*)(sc + (r4 + 8) * SCSTR + colg) = make_float2(acc[2], acc[3]);
        __syncthreads();
    }
    CP_WAIT0();   // drain redundant prefetch before buffers are reused
    __syncthreads();

    // ================= softmax: one warp per row =================
    {
        const int r  = wid;
        const int Lr = qbase + r + 1;
        float* srow = sc + r * SCSTR;

        float m = -1e30f;
        for (int jj = lane; jj < Lr; jj += 32) m = fmaxf(m, srow[jj]);
        #pragma unroll
        for (int o = 16; o > 0; o >>= 1) m = fmaxf(m, __shfl_xor_sync(0xffffffffu, m, o));

        float s = 0.f;
        for (int jj = lane; jj < Lr; jj += 32) {
            float p = __expf(srow[jj] - m);
            srow[jj] = p;
            s += p;
        }
        #pragma unroll
        for (int o = 16; o > 0; o >>= 1) s += __shfl_xor_sync(0xffffffffu, s, o);
        if (lane == 0) sinv[r] = 1.0f / s;

        for (int jj = Lr + lane; jj < cend; jj += 32) srow[jj] = 0.f;
    }
    __syncthreads();

    // ======= attn global write + in-place bf16 hi/lo pack =======
    {
        const int j = tid * 4;   // 512 threads x 4 = 2048 cols
        #pragma unroll 1
        for (int r = 0; r < TQ; ++r) {
            const float invr = sinv[r];
            float* srow = sc + r * SCSTR;
            float4* arow4 = attng ? (float4*)(attng + ((size_t)bh * SDIM + qbase + r) * SDIM) : (float4*)0;
            if (j < cend) {
                float4 p = *(float4*)(srow + j);
                if (arow4) arow4[tid] = make_float4(p.x * invr, p.y * invr, p.z * invr, p.w * invr);
                uint4 pk;
                pk.x = pack_hl(p.x); pk.y = pack_hl(p.y);
                pk.z = pack_hl(p.z); pk.w = pack_hl(p.w);
                *(uint4*)(srow + j) = pk;
            } else if (arow4) {
                arow4[tid] = make_float4(0.f, 0.f, 0.f, 0.f);
            }
        }
    }
    __syncthreads();

    // ================= PV (split-K across warp halves) =================
    const uint32_t* scp = (const uint32_t*)sc;
    float oacc[4] = {0.f, 0.f, 0.f, 0.f};
    const int dcol = ((wid & 7) << 3) + (lane >> 2);
    const int khalf = (wid >= 8) ? 64 : 0;

    stageV(0, 0);
    CP_COMMIT();
    for (int c = 0; c < nChunks; ++c) {
        int cn = c + 1 < nChunks ? c + 1 : nChunks - 1;
        stageV((c + 1) & 1, cn);
        CP_COMMIT();
        CP_WAIT1();
        __syncthreads();

        const uint16_t* hib = stg + (c & 1) * 2 * BUFU;
        const uint16_t* lob = hib + BUFU;

        #pragma unroll
        for (int ks = 0; ks < 4; ++ks) {
            const int jb = (c << 7) + khalf + ks * 16;
            uint2 w01 = *(const uint2*)(scp + r4 * SCSTR + jb + c0);
            uint2 w23 = *(const uint2*)(scp + (r4 + 8) * SCSTR + jb + c0);
            uint2 w45 = *(const uint2*)(scp + r4 * SCSTR + jb + c0 + 8);
            uint2 w67 = *(const uint2*)(scp + (r4 + 8) * SCSTR + jb + c0 + 8);
            uint32_t ah[4], al[4];
            ah[0] = __byte_perm(w01.x, w01.y, 0x5410); al[0] = __byte_perm(w01.x, w01.y, 0x7632);
            ah[1] = __byte_perm(w23.x, w23.y, 0x5410); al[1] = __byte_perm(w23.x, w23.y, 0x7632);
            ah[2] = __byte_perm(w45.x, w45.y, 0x5410); al[2] = __byte_perm(w45.x, w45.y, 0x7632);
            ah[3] = __byte_perm(w67.x, w67.y, 0x5410); al[3] = __byte_perm(w67.x, w67.y, 0x7632);

            const int kk = khalf + ks * 16 + k0;
            uint32_t bh2[2], bl2[2];
            bh2[0] = *(const uint32_t*)(hib + dcol * VSTR + kk);
            bh2[1] = *(const uint32_t*)(hib + dcol * VSTR + kk + 8);
            bl2[0] = *(const uint32_t*)(lob + dcol * VSTR + kk);
            bl2[1] = *(const uint32_t*)(lob + dcol * VSTR + kk + 8);

            mma16816(oacc, ah, bh2);
            mma16816(oacc, al, bh2);
            mma16816(oacc, ah, bl2);
        }
        __syncthreads();
    }

    // reduce warp halves via qs (free by now), then write output
    if (wid >= 8)
        *(float4*)(qs + (((wid - 8) << 5) + lane) * 4) = make_float4(oacc[0], oacc[1], oacc[2], oacc[3]);
    __syncthreads();
    if (wid < 8) {
        float4 o2 = *(float4*)(qs + ((wid << 5) + lane) * 4);
        oacc[0] += o2.x; oacc[1] += o2.y; oacc[2] += o2.z; oacc[3] += o2.w;

        float* orow = outg + headoff + (size_t)qbase * DDIM;
        const int dc = (wid << 3) + c0;
        *(float2*)(orow + r4 * DDIM + dc) =
            make_float2(oacc[0] * sinv[r4], oacc[1] * sinv[r4]);
        *(float2*)(orow + (r4 + 8) * DDIM + dc) =
            make_float2(oacc[2] * sinv[r4 + 8], oacc[3] * sinv[r4 + 8]);
    }
}

extern "C" void kernel_launch(void* const* d_in, const int* in_sizes, int n_in,
                              void* d_out, int out_size) {
    const float* q = (const float*)d_in[0];
    const float* k = (const float*)d_in[1];
    const float* v = (const float*)d_in[2];

    float* out = (float*)d_out;
    const long long OUT_E  = 64LL * 2048 * 64;
    const long long ATTN_E = 64LL * 2048 * 2048;
    float* attn = ((long long)out_size >= OUT_E + ATTN_E) ? out + OUT_E : nullptr;

    // pre-convert K and V^T to bf16 hi/lo scratch
    conv_k_kernel<<<8192, 256>>>(k);                 // 64*2048*64/4/256
    {
        dim3 g(32, 64);
        conv_vt_kernel<<<g, 256>>>(v);
    }

    cudaFuncSetAttribute(attn_mma_kernel,
                         cudaFuncAttributeMaxDynamicSharedMemorySize, SMEM_BYTES);
    dim3 grid(SDIM / TQ, 64);
    attn_mma_kernel<<<grid, NTHREADS, SMEM_BYTES>>>(q, out, attn);
}